// round 6
// baseline (speedup 1.0000x reference)
#include <cuda_runtime.h>
#include <cstdint>

// LIF scan, two-pass to unmix DRAM read/write streams:
//   Pass 1: read x [B,T,N] f32, run recurrence, pack spikes to 1 bit/elem
//           (8 MB scratch) via warp ballots  -> ~pure-READ stream.
//   Pass 2: expand bits (L2-hot) to f32 {0,1} output -> ~pure-WRITE stream.

#define B_DIM 64
#define T_DIM 128
#define N_DIM 8192
#define N4_PER_B (N_DIM / 4)            // 2048 float4 per time-row
#define WCOLS (B_DIM * N4_PER_B / 32)   // 4096 warp-columns

// 128 t-steps x 4096 warp-cols x uint4 = 8 MB scratch (static, allowed)
__device__ uint4 g_spike_bits[T_DIM * WCOLS];

__global__ void __launch_bounds__(256) lif_pack_kernel(const float4* __restrict__ x) {
    const float V_TH = 1.0f;
    const float TAU  = 0.25f;

    int tid  = blockIdx.x * blockDim.x + threadIdx.x;  // 0 .. B*N/4-1
    int lane = tid & 31;
    int wcol = tid >> 5;                                // global warp-column
    int b    = tid >> 11;
    int n4   = tid & (N4_PER_B - 1);

    long base = (long)b * T_DIM * N4_PER_B + n4;

    float mx = 0.f, my = 0.f, mz = 0.f, mw = 0.f;

#pragma unroll 8
    for (int t = 0; t < T_DIM; ++t) {
        float4 v = x[base + (long)t * N4_PER_B];

        mx = TAU * mx + v.x;
        my = TAU * my + v.y;
        mz = TAU * mz + v.z;
        mw = TAU * mw + v.w;

        bool sx = mx > V_TH;
        bool sy = my > V_TH;
        bool sz = mz > V_TH;
        bool sw = mw > V_TH;

        mx = sx ? 0.0f : mx;
        my = sy ? 0.0f : my;
        mz = sz ? 0.0f : mz;
        mw = sw ? 0.0f : mw;

        unsigned bx = __ballot_sync(0xFFFFFFFFu, sx);
        unsigned by = __ballot_sync(0xFFFFFFFFu, sy);
        unsigned bz = __ballot_sync(0xFFFFFFFFu, sz);
        unsigned bw = __ballot_sync(0xFFFFFFFFu, sw);

        if (lane == 0)
            g_spike_bits[t * WCOLS + wcol] = make_uint4(bx, by, bz, bw);
    }
}

// Fully parallel over (b, t, n4): pure write stream, scratch reads hit L2.
__global__ void __launch_bounds__(256) lif_expand_kernel(float4* __restrict__ out) {
    int tid = blockIdx.x * blockDim.x + threadIdx.x;   // 0 .. B*T*N/4-1
    int n4  = tid & (N4_PER_B - 1);
    int t   = (tid >> 11) & (T_DIM - 1);
    int b   = tid >> 18;
    int lane = n4 & 31;
    int wcol = (b * N4_PER_B + n4) >> 5;

    uint4 w = g_spike_bits[t * WCOLS + wcol];          // broadcast within warp

    float4 s;
    s.x = ((w.x >> lane) & 1u) ? 1.0f : 0.0f;
    s.y = ((w.y >> lane) & 1u) ? 1.0f : 0.0f;
    s.z = ((w.z >> lane) & 1u) ? 1.0f : 0.0f;
    s.w = ((w.w >> lane) & 1u) ? 1.0f : 0.0f;

    out[(long)b * T_DIM * N4_PER_B + (long)t * N4_PER_B + n4] = s;
}

extern "C" void kernel_launch(void* const* d_in, const int* in_sizes, int n_in,
                              void* d_out, int out_size) {
    const float4* x = (const float4*)d_in[0];
    float4* out     = (float4*)d_out;

    {   // Pass 1: recurrence + bit-pack (read-dominated)
        int total = B_DIM * N4_PER_B;          // 131072 threads
        lif_pack_kernel<<<total / 256, 256>>>(x);
    }
    {   // Pass 2: expand bits to f32 (write-dominated)
        int total = B_DIM * T_DIM * N4_PER_B;  // 16777216 threads
        lif_expand_kernel<<<total / 256, 256>>>(out);
    }
}